// round 13
// baseline (speedup 1.0000x reference)
#include <cuda_runtime.h>
#include <cuda_fp16.h>
#include <cstdint>

#define T_TOK 16384
#define DIN   1280
#define DOUT  3840
#define KEXTP 128           // padded extension cols (16 shared + 96 routed + 16 zero)
#define KTOT  1408          // 1280 + 128 (cols 1392..1407 zero)
#define NEXP  6
#define TOPK  3
#define STAGES 3
#define CH    64            // K halves per chunk/stage
#define SROWH 72            // smem row stride in halves (conflict-free scalar LDS, 16B-aligned)

// ------- scratch (no cudaMalloc allowed) -------
__device__ __align__(16) __half g_X [(size_t)T_TOK * DIN];    // fp16 x
__device__ __align__(16) __half g_G [(size_t)T_TOK * KEXTP];  // gated fp16 ext (pad zero)
__device__ __align__(16) __half g_Bt[(size_t)DOUT * KTOT];    // B^T main fp16 (pad zero)
__device__ __align__(16) __half g_B1[(size_t)128 * DIN];      // B^T prep fp16 (112 real)
__device__ __align__(16) float  g_CW[(size_t)T_TOK * NEXP];   // per-token gate weights

__device__ __forceinline__ uint32_t smem_u32(const void* p) {
    uint32_t a; asm("{ .reg .u64 t; cvta.to.shared.u64 t, %1; cvt.u32.u64 %0, t; }" : "=r"(a) : "l"(p));
    return a;
}
#define CP16(dst, src) asm volatile("cp.async.cg.shared.global [%0], [%1], 16;" :: "r"(dst), "l"(src))
#define CP_COMMIT()    asm volatile("cp.async.commit_group;" ::: "memory")
#define CP_WAIT1()     asm volatile("cp.async.wait_group 1;" ::: "memory")

__device__ __forceinline__ void mma_f16(float c[4],
    uint32_t a0, uint32_t a1, uint32_t a2, uint32_t a3, uint32_t b0, uint32_t b1)
{
    asm volatile(
        "mma.sync.aligned.m16n8k16.row.col.f32.f16.f16.f32 "
        "{%0,%1,%2,%3}, {%4,%5,%6,%7}, {%8,%9}, {%0,%1,%2,%3};\n"
        : "+f"(c[0]), "+f"(c[1]), "+f"(c[2]), "+f"(c[3])
        : "r"(a0), "r"(a1), "r"(a2), "r"(a3), "r"(b0), "r"(b1));
}

// 128x128 CTA tile, 8 warps (2x4 -> warp 64x32), K chunk 64, 3-stage cp.async.
// A chunks < CX from A1 (halves, stride sA1), >= CX from A2 (stride sA2, rebased).
// MODE 0: fp32 out + bias.  MODE 1: gated fp16 out to g_G (stride KEXTP).
template<int NK, int CX, int MODE>
__global__ void __launch_bounds__(256, 2) gemm_k(
    const __half* __restrict__ A1, int sA1,
    const __half* __restrict__ A2, int sA2,
    const __half* __restrict__ B,  int sB,
    const float* __restrict__ bias,
    float* __restrict__ outF, int sOut)
{
    constexpr int STG = 128 * SROWH;             // halves per operand stage
    extern __shared__ __half smh[];
    __half* As = smh;                            // [STAGES][STG]
    __half* Bs = smh + STAGES * STG;
    const uint32_t smA = smem_u32(As);
    const uint32_t smB = smem_u32(Bs);

    const int tid  = threadIdx.x;
    const int bm   = blockIdx.y * 128, bn = blockIdx.x * 128;
    const int warp = tid >> 5, lane = tid & 31;
    const int wm   = (warp & 1) * 64, wn = (warp >> 1) * 32;
    const int grp  = lane >> 2, tig = lane & 3;
    const int lrow = tid >> 1;                   // 0..127
    const int fb   = (tid & 1);                  // which 64B half of the 128B row

    auto issue = [&](int c) {
        const int slot = c % STAGES;
        const __half* asrc = (c < CX)
            ? A1 + (size_t)(bm + lrow) * sA1 + c * CH
            : A2 + (size_t)(bm + lrow) * sA2 + (c - CX) * CH;
        const __half* bsrc = B + (size_t)(bn + lrow) * sB + c * CH;
        const uint32_t so = (uint32_t)(slot * STG + lrow * SROWH) * 2 + fb * 64;
        #pragma unroll
        for (int f = 0; f < 4; f++) {
            CP16(smA + so + f * 16, asrc + fb * 32 + f * 8);
            CP16(smB + so + f * 16, bsrc + fb * 32 + f * 8);
        }
    };

    float acc[4][4][4];
    #pragma unroll
    for (int i = 0; i < 4; i++)
        #pragma unroll
        for (int j = 0; j < 4; j++)
            #pragma unroll
            for (int k = 0; k < 4; k++) acc[i][j][k] = 0.f;

    issue(0); CP_COMMIT();
    issue(1); CP_COMMIT();

    for (int kc = 0; kc < NK; kc++) {
        CP_WAIT1();
        __syncthreads();
        if (kc + 2 < NK) { issue(kc + 2); }
        CP_COMMIT();

        const int slot = kc % STAGES;
        const __half* Ab = As + slot * STG;
        const __half* Bb = Bs + slot * STG;
        #pragma unroll
        for (int ks = 0; ks < 4; ks++) {
            const int kb = ks * 16;
            uint32_t af[4][4], bf[4][2];
            #pragma unroll
            for (int mi = 0; mi < 4; mi++) {
                const int r0 = (wm + mi * 16 + grp) * SROWH + kb + 2 * tig;
                const int r1 = r0 + 8 * SROWH;
                af[mi][0] = *reinterpret_cast<const uint32_t*>(Ab + r0);
                af[mi][1] = *reinterpret_cast<const uint32_t*>(Ab + r1);
                af[mi][2] = *reinterpret_cast<const uint32_t*>(Ab + r0 + 8);
                af[mi][3] = *reinterpret_cast<const uint32_t*>(Ab + r1 + 8);
            }
            #pragma unroll
            for (int ni = 0; ni < 4; ni++) {
                const int n0 = (wn + ni * 8 + grp) * SROWH + kb + 2 * tig;
                bf[ni][0] = *reinterpret_cast<const uint32_t*>(Bb + n0);
                bf[ni][1] = *reinterpret_cast<const uint32_t*>(Bb + n0 + 8);
            }
            #pragma unroll
            for (int mi = 0; mi < 4; mi++)
                #pragma unroll
                for (int ni = 0; ni < 4; ni++)
                    mma_f16(acc[mi][ni], af[mi][0], af[mi][1], af[mi][2], af[mi][3],
                            bf[ni][0], bf[ni][1]);
        }
    }

    #pragma unroll
    for (int mi = 0; mi < 4; mi++) {
        #pragma unroll
        for (int ni = 0; ni < 4; ni++) {
            const int r0  = bm + wm + mi * 16 + grp;
            const int col = bn + wn + ni * 8 + tig * 2;
            if (MODE == 0) {
                const float b0 = bias[col], b1 = bias[col + 1];
                float2 v0 = make_float2(acc[mi][ni][0] + b0, acc[mi][ni][1] + b1);
                float2 v1 = make_float2(acc[mi][ni][2] + b0, acc[mi][ni][3] + b1);
                *reinterpret_cast<float2*>(outF + (size_t)r0 * sOut + col)       = v0;
                *reinterpret_cast<float2*>(outF + (size_t)(r0 + 8) * sOut + col) = v1;
            } else {
                float g0 = 1.f, g1 = 1.f;
                if (col >= 112)     { g0 = 0.f; g1 = 0.f; }
                else if (col >= 16) {
                    const int e = (col - 16) >> 4;
                    g0 = g_CW[(size_t)r0 * NEXP + e];
                    g1 = g_CW[(size_t)(r0 + 8) * NEXP + e];
                }
                __half2 h0 = __floats2half2_rn(acc[mi][ni][0] * g0, acc[mi][ni][1] * g0);
                __half2 h1 = __floats2half2_rn(acc[mi][ni][2] * g1, acc[mi][ni][3] * g1);
                *reinterpret_cast<__half2*>(g_G + (size_t)r0 * KEXTP + col)       = h0;
                *reinterpret_cast<__half2*>(g_G + (size_t)(r0 + 8) * KEXTP + col) = h1;
            }
        }
    }
}

// ---- stage B^T main: g_Bt[n][k] fp16, k rows 1392..1407 zero ----
__global__ void stage_Bt_k(const float* __restrict__ bw, const float* __restrict__ sw2,
                           const float* __restrict__ rw2)
{
    __shared__ float t[32][33];
    const int k0 = blockIdx.x * 32, n0 = blockIdx.y * 32;
    const int tx = threadIdx.x, ty = threadIdx.y;
    #pragma unroll
    for (int i = 0; i < 4; i++) {
        const int k = k0 + ty + i * 8;
        float v = 0.f;
        if (k < 1280)      v = bw [(size_t)k * DOUT + n0 + tx];
        else if (k < 1296) v = sw2[(size_t)(k - 1280) * DOUT + n0 + tx];
        else if (k < 1392) v = rw2[(size_t)(k - 1296) * DOUT + n0 + tx];
        t[ty + i * 8][tx] = v;
    }
    __syncthreads();
    #pragma unroll
    for (int i = 0; i < 4; i++)
        g_Bt[(size_t)(n0 + ty + i * 8) * KTOT + k0 + tx] = __float2half_rn(t[tx][ty + i * 8]);
}

// ---- stage B^T prep: g_B1[n][k] fp16, rows 112..127 zero ----
__global__ void stage_B1_k(const float* __restrict__ sw1, const float* __restrict__ rw1)
{
    const int k = blockIdx.x * 128 + threadIdx.x;
    const int n = blockIdx.y;
    float v = 0.f;
    if (n < 16)       v = sw1[(size_t)k * 16 + n];
    else if (n < 112) v = rw1[(size_t)((n - 16) >> 4) * DIN * 16 + (size_t)k * 16 + ((n - 16) & 15)];
    g_B1[(size_t)n * DIN + k] = __float2half_rn(v);
}

// ---- router (r10 version): rtw transposed in smem, float4 x loads,
//      exact fp32 logits + top-3 -> g_CW; coalesced fp16 x -> g_X ----
__global__ void __launch_bounds__(256) router_k(
    const float* __restrict__ x, const float* __restrict__ rtw, const float* __restrict__ rtb)
{
    __shared__ __align__(16) float s_rtw[NEXP * DIN];   // [e][k]
    const int tid  = threadIdx.x;
    const int lane = tid & 31;

    for (int i = tid; i < DIN * NEXP; i += 256) {
        const int k = i / NEXP, e = i - k * NEXP;
        s_rtw[e * DIN + k] = rtw[i];
    }
    __syncthreads();

    const int gw = (blockIdx.x * 256 + tid) >> 5;
    const float* xr = x + (size_t)gw * DIN;
    float p[NEXP];
    #pragma unroll
    for (int e = 0; e < NEXP; e++) p[e] = 0.f;

    #pragma unroll
    for (int i = 0; i < DIN / 128; i++) {
        const int k = i * 128 + lane * 4;
        const float4 xv = *reinterpret_cast<const float4*>(xr + k);
        __half2 h01 = __floats2half2_rn(xv.x, xv.y);
        __half2 h23 = __floats2half2_rn(xv.z, xv.w);
        uint2 pk;
        pk.x = *reinterpret_cast<uint32_t*>(&h01);
        pk.y = *reinterpret_cast<uint32_t*>(&h23);
        *reinterpret_cast<uint2*>(g_X + (size_t)gw * DIN + k) = pk;
        #pragma unroll
        for (int e = 0; e < NEXP; e++) {
            const float4 wv = *reinterpret_cast<const float4*>(s_rtw + e * DIN + k);
            p[e] += xv.x * wv.x + xv.y * wv.y + xv.z * wv.z + xv.w * wv.w;
        }
    }
    #pragma unroll
    for (int e = 0; e < NEXP; e++) {
        #pragma unroll
        for (int o = 16; o > 0; o >>= 1) p[e] += __shfl_xor_sync(0xffffffffu, p[e], o);
        p[e] += rtb[e];
    }
    float mx = p[0];
    #pragma unroll
    for (int e = 1; e < NEXP; e++) mx = fmaxf(mx, p[e]);
    float ge[NEXP], ssum = 0.f;
    #pragma unroll
    for (int e = 0; e < NEXP; e++) { ge[e] = expf(p[e] - mx); ssum += ge[e]; }
    const float inv = 1.f / ssum;
    float cw[NEXP], tmp[NEXP];
    #pragma unroll
    for (int e = 0; e < NEXP; e++) { cw[e] = 0.f; tmp[e] = ge[e]; }
    #pragma unroll
    for (int it = 0; it < TOPK; it++) {
        int bi = 0; float bv = tmp[0];
        #pragma unroll
        for (int e = 1; e < NEXP; e++) if (tmp[e] > bv) { bv = tmp[e]; bi = e; }
        cw[bi] = ge[bi] * inv; tmp[bi] = -1.f;
    }
    if (lane < NEXP) {
        float v = 0.f;
        #pragma unroll
        for (int e = 0; e < NEXP; e++) if (lane == e) v = cw[e];
        g_CW[(size_t)gw * NEXP + lane] = v;
    }
}

extern "C" void kernel_launch(void* const* d_in, const int* in_sizes, int n_in,
                              void* d_out, int out_size)
{
    const float* x   = (const float*)d_in[0];
    const float* bw  = (const float*)d_in[1];
    const float* bb  = (const float*)d_in[2];
    const float* sw1 = (const float*)d_in[3];
    const float* sw2 = (const float*)d_in[4];
    const float* rw1 = (const float*)d_in[5];
    const float* rw2 = (const float*)d_in[6];
    const float* rtw = (const float*)d_in[7];
    const float* rtb = (const float*)d_in[8];
    float* out = (float*)d_out;

    void *pX, *pG, *pBt, *pB1;
    cudaGetSymbolAddress(&pX,  g_X);
    cudaGetSymbolAddress(&pG,  g_G);
    cudaGetSymbolAddress(&pBt, g_Bt);
    cudaGetSymbolAddress(&pB1, g_B1);

    constexpr int SMSZ = STAGES * 128 * SROWH * 2 * 2;   // 110592 B
    cudaFuncSetAttribute(gemm_k<20, 99, 1>, cudaFuncAttributeMaxDynamicSharedMemorySize, SMSZ);
    cudaFuncSetAttribute(gemm_k<22, 20, 0>, cudaFuncAttributeMaxDynamicSharedMemorySize, SMSZ);

    // 1) stage fp16 operands
    stage_Bt_k<<<dim3(KTOT / 32, DOUT / 32), dim3(32, 8)>>>(bw, sw2, rw2);
    stage_B1_k<<<dim3(DIN / 128, 128), 128>>>(sw1, rw1);
    // 2) router: exact-fp32 gates -> g_CW, fp16 x -> g_X
    router_k<<<T_TOK / 8, 256>>>(x, rtw, rtb);
    // 3) prep GEMM with fused gating epilogue: g_G = gate(g_X @ W1cat)
    gemm_k<20, 99, 1><<<dim3(1, T_TOK / 128), 256, SMSZ>>>(
        (const __half*)pX, DIN, (const __half*)pX, DIN, (const __half*)pB1, DIN,
        nullptr, nullptr, 0);
    // 4) main GEMM: out = [g_X | g_G] @ g_Bt^T + bias
    gemm_k<22, 20, 0><<<dim3(DOUT / 128, T_TOK / 128), 256, SMSZ>>>(
        (const __half*)pX, DIN, (const __half*)pG, KEXTP, (const __half*)pBt, KTOT,
        bb, out, DOUT);
}

// round 15
// speedup vs baseline: 1.1020x; 1.1020x over previous
#include <cuda_runtime.h>
#include <cuda_fp16.h>
#include <cstdint>

#define T_TOK 16384
#define DIN   1280
#define DOUT  3840
#define KEXTP 128           // padded extension cols (16 shared + 96 routed + 16 zero)
#define KTOT  1408          // 1280 + 128 (cols 1392..1407 zero)
#define NEXP  6
#define TOPK  3
#define STAGES 4
#define CH    32            // K halves per chunk/stage
#define SROWH 40            // smem row stride in halves (conflict-free scalar LDS, 16B-aligned)

// ------- scratch (no cudaMalloc allowed) -------
__device__ __align__(16) __half g_X  [(size_t)T_TOK * DIN];    // fp16 x
__device__ __align__(16) __half g_G  [(size_t)T_TOK * KEXTP];  // gated fp16 ext (pad zero)
__device__ __align__(16) __half g_Bt [(size_t)DOUT * KTOT];    // B^T main fp16 (pad zero)
__device__ __align__(16) __half g_B1 [(size_t)128 * DIN];      // B^T prep fp16 (112 real)
__device__ __align__(16) float  g_CW [(size_t)T_TOK * NEXP];   // per-token gate weights
__device__ __align__(16) float  g_RTW[(size_t)NEXP * DIN];     // router weights, transposed [e][k]

__device__ __forceinline__ uint32_t smem_u32(const void* p) {
    uint32_t a; asm("{ .reg .u64 t; cvta.to.shared.u64 t, %1; cvt.u32.u64 %0, t; }" : "=r"(a) : "l"(p));
    return a;
}
#define CP16(dst, src) asm volatile("cp.async.cg.shared.global [%0], [%1], 16;" :: "r"(dst), "l"(src))
#define CP_COMMIT()    asm volatile("cp.async.commit_group;" ::: "memory")
#define CP_WAIT2()     asm volatile("cp.async.wait_group 2;" ::: "memory")

__device__ __forceinline__ void mma_f16(float c[4],
    uint32_t a0, uint32_t a1, uint32_t a2, uint32_t a3, uint32_t b0, uint32_t b1)
{
    asm volatile(
        "mma.sync.aligned.m16n8k16.row.col.f32.f16.f16.f32 "
        "{%0,%1,%2,%3}, {%4,%5,%6,%7}, {%8,%9}, {%0,%1,%2,%3};\n"
        : "+f"(c[0]), "+f"(c[1]), "+f"(c[2]), "+f"(c[3])
        : "r"(a0), "r"(a1), "r"(a2), "r"(a3), "r"(b0), "r"(b1));
}

// r6/r10-winner GEMM: 128x128 CTA tile, 8 warps (2x4 -> warp 64x32), K chunk 32, 4-stage cp.async.
// A chunks < CX from A1 (halves, stride sA1), >= CX from A2 (stride sA2, rebased).
// MODE 0: fp32 out + bias.  MODE 1: gated fp16 out to g_G (stride KEXTP).
template<int NK, int CX, int MODE>
__global__ void __launch_bounds__(256, 2) gemm_k(
    const __half* __restrict__ A1, int sA1,
    const __half* __restrict__ A2, int sA2,
    const __half* __restrict__ B,  int sB,
    const float* __restrict__ bias,
    float* __restrict__ outF, int sOut)
{
    extern __shared__ __half smh[];
    __half* As = smh;                            // [STAGES][128*SROWH]
    __half* Bs = smh + STAGES * 128 * SROWH;
    const uint32_t smA = smem_u32(As);
    const uint32_t smB = smem_u32(Bs);

    const int tid  = threadIdx.x;
    const int bm   = blockIdx.y * 128, bn = blockIdx.x * 128;
    const int warp = tid >> 5, lane = tid & 31;
    const int wm   = (warp & 1) * 64, wn = (warp >> 1) * 32;
    const int grp  = lane >> 2, tig = lane & 3;
    const int lrow = tid >> 1;                   // 0..127
    const int fb   = (tid & 1);                  // half-of-row selector

    auto issue = [&](int c) {
        const int slot = c & (STAGES - 1);
        const __half* asrc = (c < CX)
            ? A1 + (size_t)(bm + lrow) * sA1 + c * CH
            : A2 + (size_t)(bm + lrow) * sA2 + (c - CX) * CH;
        const __half* bsrc = B + (size_t)(bn + lrow) * sB + c * CH;
        const uint32_t so = (uint32_t)(slot * 128 * SROWH + lrow * SROWH) * 2 + fb * 32;
        #pragma unroll
        for (int f = 0; f < 2; f++) {
            CP16(smA + so + f * 16, asrc + fb * 16 + f * 8);
            CP16(smB + so + f * 16, bsrc + fb * 16 + f * 8);
        }
    };

    float acc[4][4][4];
    #pragma unroll
    for (int i = 0; i < 4; i++)
        #pragma unroll
        for (int j = 0; j < 4; j++)
            #pragma unroll
            for (int k = 0; k < 4; k++) acc[i][j][k] = 0.f;

    #pragma unroll
    for (int s = 0; s < STAGES - 1; s++) { issue(s); CP_COMMIT(); }

    for (int kc = 0; kc < NK; kc++) {
        CP_WAIT2();
        __syncthreads();
        if (kc + STAGES - 1 < NK) issue(kc + STAGES - 1);
        CP_COMMIT();

        const int slot = kc & (STAGES - 1);
        const __half* Ab = As + slot * 128 * SROWH;
        const __half* Bb = Bs + slot * 128 * SROWH;
        #pragma unroll
        for (int ks = 0; ks < 2; ks++) {
            const int kb = ks * 16;
            uint32_t af[4][4], bf[4][2];
            #pragma unroll
            for (int mi = 0; mi < 4; mi++) {
                const int r0 = (wm + mi * 16 + grp) * SROWH + kb + 2 * tig;
                const int r1 = r0 + 8 * SROWH;
                af[mi][0] = *reinterpret_cast<const uint32_t*>(Ab + r0);
                af[mi][1] = *reinterpret_cast<const uint32_t*>(Ab + r1);
                af[mi][2] = *reinterpret_cast<const uint32_t*>(Ab + r0 + 8);
                af[mi][3] = *reinterpret_cast<const uint32_t*>(Ab + r1 + 8);
            }
            #pragma unroll
            for (int ni = 0; ni < 4; ni++) {
                const int n0 = (wn + ni * 8 + grp) * SROWH + kb + 2 * tig;
                bf[ni][0] = *reinterpret_cast<const uint32_t*>(Bb + n0);
                bf[ni][1] = *reinterpret_cast<const uint32_t*>(Bb + n0 + 8);
            }
            #pragma unroll
            for (int mi = 0; mi < 4; mi++)
                #pragma unroll
                for (int ni = 0; ni < 4; ni++)
                    mma_f16(acc[mi][ni], af[mi][0], af[mi][1], af[mi][2], af[mi][3],
                            bf[ni][0], bf[ni][1]);
        }
    }

    #pragma unroll
    for (int mi = 0; mi < 4; mi++) {
        #pragma unroll
        for (int ni = 0; ni < 4; ni++) {
            const int r0  = bm + wm + mi * 16 + grp;
            const int col = bn + wn + ni * 8 + tig * 2;
            if (MODE == 0) {
                const float b0 = bias[col], b1 = bias[col + 1];
                float2 v0 = make_float2(acc[mi][ni][0] + b0, acc[mi][ni][1] + b1);
                float2 v1 = make_float2(acc[mi][ni][2] + b0, acc[mi][ni][3] + b1);
                *reinterpret_cast<float2*>(outF + (size_t)r0 * sOut + col)       = v0;
                *reinterpret_cast<float2*>(outF + (size_t)(r0 + 8) * sOut + col) = v1;
            } else {
                float g0 = 1.f, g1 = 1.f;
                if (col >= 112)     { g0 = 0.f; g1 = 0.f; }
                else if (col >= 16) {
                    const int e = (col - 16) >> 4;
                    g0 = g_CW[(size_t)r0 * NEXP + e];
                    g1 = g_CW[(size_t)(r0 + 8) * NEXP + e];
                }
                __half2 h0 = __floats2half2_rn(acc[mi][ni][0] * g0, acc[mi][ni][1] * g0);
                __half2 h1 = __floats2half2_rn(acc[mi][ni][2] * g1, acc[mi][ni][3] * g1);
                *reinterpret_cast<__half2*>(g_G + (size_t)r0 * KEXTP + col)       = h0;
                *reinterpret_cast<__half2*>(g_G + (size_t)(r0 + 8) * KEXTP + col) = h1;
            }
        }
    }
}

// ---- stage B^T main: g_Bt[n][k] fp16, k rows 1392..1407 zero ----
__global__ void stage_Bt_k(const float* __restrict__ bw, const float* __restrict__ sw2,
                           const float* __restrict__ rw2)
{
    __shared__ float t[32][33];
    const int k0 = blockIdx.x * 32, n0 = blockIdx.y * 32;
    const int tx = threadIdx.x, ty = threadIdx.y;
    #pragma unroll
    for (int i = 0; i < 4; i++) {
        const int k = k0 + ty + i * 8;
        float v = 0.f;
        if (k < 1280)      v = bw [(size_t)k * DOUT + n0 + tx];
        else if (k < 1296) v = sw2[(size_t)(k - 1280) * DOUT + n0 + tx];
        else if (k < 1392) v = rw2[(size_t)(k - 1296) * DOUT + n0 + tx];
        t[ty + i * 8][tx] = v;
    }
    __syncthreads();
    #pragma unroll
    for (int i = 0; i < 4; i++)
        g_Bt[(size_t)(n0 + ty + i * 8) * KTOT + k0 + tx] = __float2half_rn(t[tx][ty + i * 8]);
}

// ---- stage B^T prep: g_B1[n][k] fp16, rows 112..127 zero; also transpose rtw -> g_RTW ----
__global__ void stage_B1_k(const float* __restrict__ sw1, const float* __restrict__ rw1,
                           const float* __restrict__ rtw)
{
    const int k = blockIdx.x * 128 + threadIdx.x;
    const int n = blockIdx.y;
    float v = 0.f;
    if (n < 16)       v = sw1[(size_t)k * 16 + n];
    else if (n < 112) v = rw1[(size_t)((n - 16) >> 4) * DIN * 16 + (size_t)k * 16 + ((n - 16) & 15)];
    g_B1[(size_t)n * DIN + k] = __float2half_rn(v);
    // transpose rtw once: g_RTW[e][k] = rtw[k][e]  (rows 0..5 of the grid's y-dim)
    if (n < NEXP)
        g_RTW[(size_t)n * DIN + k] = rtw[(size_t)k * NEXP + n];
}

// ---- router v6b: smem fill = bound-checked float4 copy of pre-transposed g_RTW;
//      hot loop / reduction / softmax / top-3 identical to r10 ----
__global__ void __launch_bounds__(256) router_k(
    const float* __restrict__ x, const float* __restrict__ rtb)
{
    __shared__ __align__(16) float s_rtw[NEXP * DIN];   // [e][k], 30720 B
    const int tid  = threadIdx.x;
    const int lane = tid & 31;

    // coalesced fill: 1920 float4 copies (bound-checked — 7680 not divisible by 1024)
    for (int j = tid * 4; j < NEXP * DIN; j += 256 * 4) {
        *reinterpret_cast<float4*>(s_rtw + j) =
            *reinterpret_cast<const float4*>(g_RTW + j);
    }
    __syncthreads();

    const int gw = (blockIdx.x * 256 + tid) >> 5;       // token = global warp
    const float* xr = x + (size_t)gw * DIN;
    float p[NEXP];
    #pragma unroll
    for (int e = 0; e < NEXP; e++) p[e] = 0.f;

    #pragma unroll
    for (int i = 0; i < DIN / 128; i++) {
        const int k = i * 128 + lane * 4;
        const float4 xv = *reinterpret_cast<const float4*>(xr + k);
        __half2 h01 = __floats2half2_rn(xv.x, xv.y);
        __half2 h23 = __floats2half2_rn(xv.z, xv.w);
        uint2 pk;
        pk.x = *reinterpret_cast<uint32_t*>(&h01);
        pk.y = *reinterpret_cast<uint32_t*>(&h23);
        *reinterpret_cast<uint2*>(g_X + (size_t)gw * DIN + k) = pk;
        #pragma unroll
        for (int e = 0; e < NEXP; e++) {
            const float4 wv = *reinterpret_cast<const float4*>(s_rtw + e * DIN + k);
            p[e] += xv.x * wv.x + xv.y * wv.y + xv.z * wv.z + xv.w * wv.w;
        }
    }
    #pragma unroll
    for (int e = 0; e < NEXP; e++) {
        #pragma unroll
        for (int o = 16; o > 0; o >>= 1) p[e] += __shfl_xor_sync(0xffffffffu, p[e], o);
        p[e] += rtb[e];
    }
    float mx = p[0];
    #pragma unroll
    for (int e = 1; e < NEXP; e++) mx = fmaxf(mx, p[e]);
    float ge[NEXP], ssum = 0.f;
    #pragma unroll
    for (int e = 0; e < NEXP; e++) { ge[e] = expf(p[e] - mx); ssum += ge[e]; }
    const float inv = 1.f / ssum;
    float cw[NEXP], tmp[NEXP];
    #pragma unroll
    for (int e = 0; e < NEXP; e++) { cw[e] = 0.f; tmp[e] = ge[e]; }
    #pragma unroll
    for (int it = 0; it < TOPK; it++) {
        int bi = 0; float bv = tmp[0];
        #pragma unroll
        for (int e = 1; e < NEXP; e++) if (tmp[e] > bv) { bv = tmp[e]; bi = e; }
        cw[bi] = ge[bi] * inv; tmp[bi] = -1.f;
    }
    if (lane < NEXP) {
        float v = 0.f;
        #pragma unroll
        for (int e = 0; e < NEXP; e++) if (lane == e) v = cw[e];
        g_CW[(size_t)gw * NEXP + lane] = v;
    }
}

extern "C" void kernel_launch(void* const* d_in, const int* in_sizes, int n_in,
                              void* d_out, int out_size)
{
    const float* x   = (const float*)d_in[0];
    const float* bw  = (const float*)d_in[1];
    const float* bb  = (const float*)d_in[2];
    const float* sw1 = (const float*)d_in[3];
    const float* sw2 = (const float*)d_in[4];
    const float* rw1 = (const float*)d_in[5];
    const float* rw2 = (const float*)d_in[6];
    const float* rtw = (const float*)d_in[7];
    const float* rtb = (const float*)d_in[8];
    float* out = (float*)d_out;

    void *pX, *pG, *pBt, *pB1;
    cudaGetSymbolAddress(&pX,  g_X);
    cudaGetSymbolAddress(&pG,  g_G);
    cudaGetSymbolAddress(&pBt, g_Bt);
    cudaGetSymbolAddress(&pB1, g_B1);

    constexpr int SMSZ = STAGES * 128 * SROWH * 2 * 2;   // 81920 B
    cudaFuncSetAttribute(gemm_k<40, 99, 1>, cudaFuncAttributeMaxDynamicSharedMemorySize, SMSZ);
    cudaFuncSetAttribute(gemm_k<44, 40, 0>, cudaFuncAttributeMaxDynamicSharedMemorySize, SMSZ);

    // 1) stage fp16 operands (+ one-time rtw transpose)
    stage_Bt_k<<<dim3(KTOT / 32, DOUT / 32), dim3(32, 8)>>>(bw, sw2, rw2);
    stage_B1_k<<<dim3(DIN / 128, 128), 128>>>(sw1, rw1, rtw);
    // 2) router: exact-fp32 gates -> g_CW, fp16 x -> g_X
    router_k<<<T_TOK / 8, 256>>>(x, rtb);
    // 3) prep GEMM with fused gating epilogue: g_G = gate(g_X @ W1cat)
    gemm_k<40, 99, 1><<<dim3(1, T_TOK / 128), 256, SMSZ>>>(
        (const __half*)pX, DIN, (const __half*)pX, DIN, (const __half*)pB1, DIN,
        nullptr, nullptr, 0);
    // 4) main GEMM: out = [g_X | g_G] @ g_Bt^T + bias
    gemm_k<44, 40, 0><<<dim3(DOUT / 128, T_TOK / 128), 256, SMSZ>>>(
        (const __half*)pX, DIN, (const __half*)pG, KEXTP, (const __half*)pBt, KTOT,
        bb, out, DOUT);
}

// round 16
// speedup vs baseline: 1.1074x; 1.0049x over previous
#include <cuda_runtime.h>
#include <cuda_fp16.h>
#include <cstdint>

#define T_TOK 16384
#define DIN   1280
#define DOUT  3840
#define KEXTP 128           // padded extension cols (16 shared + 96 routed + 16 zero)
#define KTOT  1408          // 1280 + 128 (cols 1392..1407 zero)
#define NEXP  6
#define TOPK  3
#define STAGES 4
#define CH    32            // K halves per chunk/stage
#define SROWH 40            // smem row stride in halves (conflict-free scalar LDS, 16B-aligned)

// fused-aux grid layout
#define NB_ROUTER 2048                          // T_TOK/8 router blocks
#define NB_BT     ((KTOT / 32) * (DOUT / 32))   // 44*120 = 5280 stage_Bt blocks
#define NB_B1     640                           // 128*1280/256 stage_B1 blocks
#define NB_AUX    (NB_ROUTER + NB_BT + NB_B1)   // 7968

// ------- scratch (no cudaMalloc allowed) -------
__device__ __align__(16) __half g_X [(size_t)T_TOK * DIN];    // fp16 x
__device__ __align__(16) __half g_G [(size_t)T_TOK * KEXTP];  // gated fp16 ext (pad zero)
__device__ __align__(16) __half g_Bt[(size_t)DOUT * KTOT];    // B^T main fp16 (pad zero)
__device__ __align__(16) __half g_B1[(size_t)128 * DIN];      // B^T prep fp16 (112 real)
__device__ __align__(16) float  g_CW[(size_t)T_TOK * NEXP];   // per-token gate weights

__device__ __forceinline__ uint32_t smem_u32(const void* p) {
    uint32_t a; asm("{ .reg .u64 t; cvta.to.shared.u64 t, %1; cvt.u32.u64 %0, t; }" : "=r"(a) : "l"(p));
    return a;
}
#define CP16(dst, src) asm volatile("cp.async.cg.shared.global [%0], [%1], 16;" :: "r"(dst), "l"(src))
#define CP_COMMIT()    asm volatile("cp.async.commit_group;" ::: "memory")
#define CP_WAIT2()     asm volatile("cp.async.wait_group 2;" ::: "memory")

__device__ __forceinline__ void mma_f16(float c[4],
    uint32_t a0, uint32_t a1, uint32_t a2, uint32_t a3, uint32_t b0, uint32_t b1)
{
    asm volatile(
        "mma.sync.aligned.m16n8k16.row.col.f32.f16.f16.f32 "
        "{%0,%1,%2,%3}, {%4,%5,%6,%7}, {%8,%9}, {%0,%1,%2,%3};\n"
        : "+f"(c[0]), "+f"(c[1]), "+f"(c[2]), "+f"(c[3])
        : "r"(a0), "r"(a1), "r"(a2), "r"(a3), "r"(b0), "r"(b1));
}

// r6/r10-winner GEMM: 128x128 CTA tile, 8 warps (2x4 -> warp 64x32), K chunk 32, 4-stage cp.async.
// A chunks < CX from A1 (halves, stride sA1), >= CX from A2 (stride sA2, rebased).
// MODE 0: fp32 out + bias.  MODE 1: gated fp16 out to g_G (stride KEXTP).
template<int NK, int CX, int MODE>
__global__ void __launch_bounds__(256, 2) gemm_k(
    const __half* __restrict__ A1, int sA1,
    const __half* __restrict__ A2, int sA2,
    const __half* __restrict__ B,  int sB,
    const float* __restrict__ bias,
    float* __restrict__ outF, int sOut)
{
    extern __shared__ __half smh[];
    __half* As = smh;                            // [STAGES][128*SROWH]
    __half* Bs = smh + STAGES * 128 * SROWH;
    const uint32_t smA = smem_u32(As);
    const uint32_t smB = smem_u32(Bs);

    const int tid  = threadIdx.x;
    const int bm   = blockIdx.y * 128, bn = blockIdx.x * 128;
    const int warp = tid >> 5, lane = tid & 31;
    const int wm   = (warp & 1) * 64, wn = (warp >> 1) * 32;
    const int grp  = lane >> 2, tig = lane & 3;
    const int lrow = tid >> 1;                   // 0..127
    const int fb   = (tid & 1);                  // half-of-row selector

    auto issue = [&](int c) {
        const int slot = c & (STAGES - 1);
        const __half* asrc = (c < CX)
            ? A1 + (size_t)(bm + lrow) * sA1 + c * CH
            : A2 + (size_t)(bm + lrow) * sA2 + (c - CX) * CH;
        const __half* bsrc = B + (size_t)(bn + lrow) * sB + c * CH;
        const uint32_t so = (uint32_t)(slot * 128 * SROWH + lrow * SROWH) * 2 + fb * 32;
        #pragma unroll
        for (int f = 0; f < 2; f++) {
            CP16(smA + so + f * 16, asrc + fb * 16 + f * 8);
            CP16(smB + so + f * 16, bsrc + fb * 16 + f * 8);
        }
    };

    float acc[4][4][4];
    #pragma unroll
    for (int i = 0; i < 4; i++)
        #pragma unroll
        for (int j = 0; j < 4; j++)
            #pragma unroll
            for (int k = 0; k < 4; k++) acc[i][j][k] = 0.f;

    #pragma unroll
    for (int s = 0; s < STAGES - 1; s++) { issue(s); CP_COMMIT(); }

    for (int kc = 0; kc < NK; kc++) {
        CP_WAIT2();
        __syncthreads();
        if (kc + STAGES - 1 < NK) issue(kc + STAGES - 1);
        CP_COMMIT();

        const int slot = kc & (STAGES - 1);
        const __half* Ab = As + slot * 128 * SROWH;
        const __half* Bb = Bs + slot * 128 * SROWH;
        #pragma unroll
        for (int ks = 0; ks < 2; ks++) {
            const int kb = ks * 16;
            uint32_t af[4][4], bf[4][2];
            #pragma unroll
            for (int mi = 0; mi < 4; mi++) {
                const int r0 = (wm + mi * 16 + grp) * SROWH + kb + 2 * tig;
                const int r1 = r0 + 8 * SROWH;
                af[mi][0] = *reinterpret_cast<const uint32_t*>(Ab + r0);
                af[mi][1] = *reinterpret_cast<const uint32_t*>(Ab + r1);
                af[mi][2] = *reinterpret_cast<const uint32_t*>(Ab + r0 + 8);
                af[mi][3] = *reinterpret_cast<const uint32_t*>(Ab + r1 + 8);
            }
            #pragma unroll
            for (int ni = 0; ni < 4; ni++) {
                const int n0 = (wn + ni * 8 + grp) * SROWH + kb + 2 * tig;
                bf[ni][0] = *reinterpret_cast<const uint32_t*>(Bb + n0);
                bf[ni][1] = *reinterpret_cast<const uint32_t*>(Bb + n0 + 8);
            }
            #pragma unroll
            for (int mi = 0; mi < 4; mi++)
                #pragma unroll
                for (int ni = 0; ni < 4; ni++)
                    mma_f16(acc[mi][ni], af[mi][0], af[mi][1], af[mi][2], af[mi][3],
                            bf[ni][0], bf[ni][1]);
        }
    }

    #pragma unroll
    for (int mi = 0; mi < 4; mi++) {
        #pragma unroll
        for (int ni = 0; ni < 4; ni++) {
            const int r0  = bm + wm + mi * 16 + grp;
            const int col = bn + wn + ni * 8 + tig * 2;
            if (MODE == 0) {
                const float b0 = bias[col], b1 = bias[col + 1];
                float2 v0 = make_float2(acc[mi][ni][0] + b0, acc[mi][ni][1] + b1);
                float2 v1 = make_float2(acc[mi][ni][2] + b0, acc[mi][ni][3] + b1);
                *reinterpret_cast<float2*>(outF + (size_t)r0 * sOut + col)       = v0;
                *reinterpret_cast<float2*>(outF + (size_t)(r0 + 8) * sOut + col) = v1;
            } else {
                float g0 = 1.f, g1 = 1.f;
                if (col >= 112)     { g0 = 0.f; g1 = 0.f; }
                else if (col >= 16) {
                    const int e = (col - 16) >> 4;
                    g0 = g_CW[(size_t)r0 * NEXP + e];
                    g1 = g_CW[(size_t)(r0 + 8) * NEXP + e];
                }
                __half2 h0 = __floats2half2_rn(acc[mi][ni][0] * g0, acc[mi][ni][1] * g0);
                __half2 h1 = __floats2half2_rn(acc[mi][ni][2] * g1, acc[mi][ni][3] * g1);
                *reinterpret_cast<__half2*>(g_G + (size_t)r0 * KEXTP + col)       = h0;
                *reinterpret_cast<__half2*>(g_G + (size_t)(r0 + 8) * KEXTP + col) = h1;
            }
        }
    }
}

// ==================== fused aux kernel: router + stage_Bt + stage_B1 ====================
// blocks [0, NB_ROUTER)                      : r10 router (in-kernel rtw transpose)
// blocks [NB_ROUTER, NB_ROUTER+NB_BT)        : stage_Bt 32x32 transpose tiles
// blocks [NB_ROUTER+NB_BT, NB_AUX)           : stage_B1 (128x1280, 256 elems/block... 640 blocks)
__global__ void __launch_bounds__(256) aux_k(
    const float* __restrict__ x,
    const float* __restrict__ rtw, const float* __restrict__ rtb,
    const float* __restrict__ bw,  const float* __restrict__ sw2,
    const float* __restrict__ rw2,
    const float* __restrict__ sw1, const float* __restrict__ rw1)
{
    __shared__ __align__(16) float s_buf[NEXP * DIN];   // 30720 B; Bt aliases first 4224 B
    const int tid = threadIdx.x;
    const int bx  = blockIdx.x;

    if (bx < NB_ROUTER) {
        // ---------------- router (r10 verbatim) ----------------
        float* s_rtw = s_buf;
        const int lane = tid & 31;
        for (int i = tid; i < DIN * NEXP; i += 256) {
            const int k = i / NEXP, e = i - k * NEXP;
            s_rtw[e * DIN + k] = rtw[i];
        }
        __syncthreads();

        const int gw = (bx * 256 + tid) >> 5;
        const float* xr = x + (size_t)gw * DIN;
        float p[NEXP];
        #pragma unroll
        for (int e = 0; e < NEXP; e++) p[e] = 0.f;

        #pragma unroll
        for (int i = 0; i < DIN / 128; i++) {
            const int k = i * 128 + lane * 4;
            const float4 xv = *reinterpret_cast<const float4*>(xr + k);
            __half2 h01 = __floats2half2_rn(xv.x, xv.y);
            __half2 h23 = __floats2half2_rn(xv.z, xv.w);
            uint2 pk;
            pk.x = *reinterpret_cast<uint32_t*>(&h01);
            pk.y = *reinterpret_cast<uint32_t*>(&h23);
            *reinterpret_cast<uint2*>(g_X + (size_t)gw * DIN + k) = pk;
            #pragma unroll
            for (int e = 0; e < NEXP; e++) {
                const float4 wv = *reinterpret_cast<const float4*>(s_rtw + e * DIN + k);
                p[e] += xv.x * wv.x + xv.y * wv.y + xv.z * wv.z + xv.w * wv.w;
            }
        }
        #pragma unroll
        for (int e = 0; e < NEXP; e++) {
            #pragma unroll
            for (int o = 16; o > 0; o >>= 1) p[e] += __shfl_xor_sync(0xffffffffu, p[e], o);
            p[e] += rtb[e];
        }
        float mx = p[0];
        #pragma unroll
        for (int e = 1; e < NEXP; e++) mx = fmaxf(mx, p[e]);
        float ge[NEXP], ssum = 0.f;
        #pragma unroll
        for (int e = 0; e < NEXP; e++) { ge[e] = expf(p[e] - mx); ssum += ge[e]; }
        const float inv = 1.f / ssum;
        float cw[NEXP], tmp[NEXP];
        #pragma unroll
        for (int e = 0; e < NEXP; e++) { cw[e] = 0.f; tmp[e] = ge[e]; }
        #pragma unroll
        for (int it = 0; it < TOPK; it++) {
            int bi = 0; float bv = tmp[0];
            #pragma unroll
            for (int e = 1; e < NEXP; e++) if (tmp[e] > bv) { bv = tmp[e]; bi = e; }
            cw[bi] = ge[bi] * inv; tmp[bi] = -1.f;
        }
        if (lane < NEXP) {
            float v = 0.f;
            #pragma unroll
            for (int e = 0; e < NEXP; e++) if (lane == e) v = cw[e];
            g_CW[(size_t)gw * NEXP + lane] = v;
        }
    } else if (bx < NB_ROUTER + NB_BT) {
        // ---------------- stage B^T main (32x32 transpose tile) ----------------
        float (*t)[33] = reinterpret_cast<float (*)[33]>(s_buf);
        const int b  = bx - NB_ROUTER;
        const int k0 = (b % (KTOT / 32)) * 32;
        const int n0 = (b / (KTOT / 32)) * 32;
        const int tx = tid & 31, ty = tid >> 5;   // (32, 8)
        #pragma unroll
        for (int i = 0; i < 4; i++) {
            const int k = k0 + ty + i * 8;
            float v = 0.f;
            if (k < 1280)      v = bw [(size_t)k * DOUT + n0 + tx];
            else if (k < 1296) v = sw2[(size_t)(k - 1280) * DOUT + n0 + tx];
            else if (k < 1392) v = rw2[(size_t)(k - 1296) * DOUT + n0 + tx];
            t[ty + i * 8][tx] = v;
        }
        __syncthreads();
        #pragma unroll
        for (int i = 0; i < 4; i++)
            g_Bt[(size_t)(n0 + ty + i * 8) * KTOT + k0 + tx] = __float2half_rn(t[tx][ty + i * 8]);
    } else {
        // ---------------- stage B^T prep (640 blocks x 256 elems) ----------------
        const int b   = bx - NB_ROUTER - NB_BT;       // 0..639
        const int n   = b / 5;                        // 0..127
        const int k   = (b % 5) * 256 + tid;          // 0..1279
        float v = 0.f;
        if (n < 16)       v = sw1[(size_t)k * 16 + n];
        else if (n < 112) v = rw1[(size_t)((n - 16) >> 4) * DIN * 16 + (size_t)k * 16 + ((n - 16) & 15)];
        g_B1[(size_t)n * DIN + k] = __float2half_rn(v);
    }
}

extern "C" void kernel_launch(void* const* d_in, const int* in_sizes, int n_in,
                              void* d_out, int out_size)
{
    const float* x   = (const float*)d_in[0];
    const float* bw  = (const float*)d_in[1];
    const float* bb  = (const float*)d_in[2];
    const float* sw1 = (const float*)d_in[3];
    const float* sw2 = (const float*)d_in[4];
    const float* rw1 = (const float*)d_in[5];
    const float* rw2 = (const float*)d_in[6];
    const float* rtw = (const float*)d_in[7];
    const float* rtb = (const float*)d_in[8];
    float* out = (float*)d_out;

    void *pX, *pG, *pBt, *pB1;
    cudaGetSymbolAddress(&pX,  g_X);
    cudaGetSymbolAddress(&pG,  g_G);
    cudaGetSymbolAddress(&pBt, g_Bt);
    cudaGetSymbolAddress(&pB1, g_B1);

    constexpr int SMSZ = STAGES * 128 * SROWH * 2 * 2;   // 81920 B
    cudaFuncSetAttribute(gemm_k<40, 99, 1>, cudaFuncAttributeMaxDynamicSharedMemorySize, SMSZ);
    cudaFuncSetAttribute(gemm_k<44, 40, 0>, cudaFuncAttributeMaxDynamicSharedMemorySize, SMSZ);

    // 1) fused aux: router (g_CW, g_X) + stage_Bt (g_Bt) + stage_B1 (g_B1) in ONE grid
    aux_k<<<NB_AUX, 256>>>(x, rtw, rtb, bw, sw2, rw2, sw1, rw1);
    // 2) prep GEMM with fused gating epilogue: g_G = gate(g_X @ W1cat)
    gemm_k<40, 99, 1><<<dim3(1, T_TOK / 128), 256, SMSZ>>>(
        (const __half*)pX, DIN, (const __half*)pX, DIN, (const __half*)pB1, DIN,
        nullptr, nullptr, 0);
    // 3) main GEMM: out = [g_X | g_G] @ g_Bt^T + bias
    gemm_k<44, 40, 0><<<dim3(DOUT / 128, T_TOK / 128), 256, SMSZ>>>(
        (const __half*)pX, DIN, (const __half*)pG, KEXTP, (const __half*)pBt, KTOT,
        bb, out, DOUT);
}